// round 2
// baseline (speedup 1.0000x reference)
#include <cuda_runtime.h>
#include <cuda_bf16.h>
#include <cstdint>

#define DEV_INLINE __device__ __forceinline__

// ---------------- problem sizes (fixed) ----------------
#define DD    2048
#define SD    512
#define MROWS 16384          // B*N = 4*4096
#define BK    64             // K elements per pipeline chunk (bf16)
#define NK_CHUNKS 32         // 2048/64
#define STAGES 3
#define STAGE_BYTES 32768    // A tile 16KB + B tile 16KB
#define DYN_SMEM (STAGES * STAGE_BYTES)

// ---------------- device scratch (static, no allocs) ----------------
__device__ __nv_bfloat16 g_Aa[(size_t)MROWS * DD];
__device__ __nv_bfloat16 g_Ah[(size_t)MROWS * DD];
__device__ __nv_bfloat16 g_Wta[(size_t)DD * DD];
__device__ __nv_bfloat16 g_Wth[(size_t)DD * DD];
__device__ float         g_Ca[(size_t)MROWS * DD];
__device__ float         g_Ch[(size_t)MROWS * DD];

struct SmallMats {
    float pre_a[4][4], pre_h[4][4];
    float res_a[4][4], res_h[4][4];
    float post_a[4][4], post_h[4][4];
    float sc_a[4], sc_h[4];
    float alpha;
};
__device__ SmallMats g_sm;

// ---------------- PTX helpers (base ISA only: sm_80+) ----------------
DEV_INLINE uint32_t smem_u32(const void* p) {
    uint32_t a;
    asm("{ .reg .u64 t; cvta.to.shared.u64 t, %1; cvt.u32.u64 %0, t; }" : "=r"(a) : "l"(p));
    return a;
}
#define SW128(o) ((o) ^ ((((uint32_t)(o)) >> 3) & 0x70u))

DEV_INLINE void cp_async16(uint32_t dst, const void* src) {
    asm volatile("cp.async.cg.shared.global [%0], [%1], 16;" :: "r"(dst), "l"(src));
}
DEV_INLINE void cp_commit() { asm volatile("cp.async.commit_group;" ::: "memory"); }
template<int N> DEV_INLINE void cp_wait() {
    asm volatile("cp.async.wait_group %0;" :: "n"(N) : "memory");
}
DEV_INLINE void ldm_x4(uint32_t* r, uint32_t addr) {
    asm volatile("ldmatrix.sync.aligned.m8n8.x4.shared.b16 {%0,%1,%2,%3}, [%4];"
                 : "=r"(r[0]), "=r"(r[1]), "=r"(r[2]), "=r"(r[3]) : "r"(addr));
}
DEV_INLINE void mma16816(float* d, const uint32_t* a, uint32_t b0, uint32_t b1) {
    asm volatile(
        "mma.sync.aligned.m16n8k16.row.col.f32.bf16.bf16.f32 "
        "{%0,%1,%2,%3}, {%4,%5,%6,%7}, {%8,%9}, {%0,%1,%2,%3};"
        : "+f"(d[0]), "+f"(d[1]), "+f"(d[2]), "+f"(d[3])
        : "r"(a[0]), "r"(a[1]), "r"(a[2]), "r"(a[3]), "r"(b0), "r"(b1));
}

// ---------------- small 4x4 matrix kernel ----------------
DEV_INLINE void softmax4(const float* L, float O[4][4]) {
    for (int s = 0; s < 4; s++) {
        float mx = L[s*4];
        for (int t = 1; t < 4; t++) mx = fmaxf(mx, L[s*4+t]);
        float sum = 0.f, e[4];
        for (int t = 0; t < 4; t++) { e[t] = expf(L[s*4+t] - mx); sum += e[t]; }
        float inv = 1.f / sum;
        for (int t = 0; t < 4; t++) O[s][t] = e[t] * inv;
    }
}
DEV_INLINE void sinkhorn4(const float* L, float P[4][4]) {
    float mx = L[0];
    for (int i = 1; i < 16; i++) mx = fmaxf(mx, L[i]);
    for (int s = 0; s < 4; s++)
        for (int t = 0; t < 4; t++) P[s][t] = expf(L[s*4+t] - mx);
    for (int it = 0; it < 20; it++) {
        for (int s = 0; s < 4; s++) {
            float rs = P[s][0] + P[s][1] + P[s][2] + P[s][3];
            float inv = 1.f / (rs + 1e-8f);
            for (int t = 0; t < 4; t++) P[s][t] *= inv;
        }
        for (int t = 0; t < 4; t++) {
            float cs = P[0][t] + P[1][t] + P[2][t] + P[3][t];
            float inv = 1.f / (cs + 1e-8f);
            for (int s = 0; s < 4; s++) P[s][t] *= inv;
        }
    }
}
__global__ void small_kernel(const float* pa, const float* ph,
                             const float* ra, const float* po_a, const float* sa,
                             const float* rh, const float* po_h, const float* sh,
                             const float* cm) {
    if (threadIdx.x != 0) return;
    softmax4(pa,   g_sm.pre_a);
    softmax4(ph,   g_sm.pre_h);
    softmax4(po_a, g_sm.post_a);
    softmax4(po_h, g_sm.post_h);
    sinkhorn4(ra,  g_sm.res_a);
    sinkhorn4(rh,  g_sm.res_h);
    for (int t = 0; t < 4; t++) { g_sm.sc_a[t] = sa[t]; g_sm.sc_h[t] = sh[t]; }
    g_sm.alpha = 1.f / (1.f + expf(-cm[0]));
}

// ---------------- W transpose + bf16 quantize -> Wt[n][k] ----------------
__global__ void wtrans_kernel(const float* __restrict__ Wa, const float* __restrict__ Wh) {
    __shared__ float tile[32][33];
    const float* W = blockIdx.z ? Wh : Wa;
    __nv_bfloat16* Wt = blockIdx.z ? g_Wth : g_Wta;
    int tx = threadIdx.x, ty = threadIdx.y;
    int x0 = blockIdx.x * 32, y0 = blockIdx.y * 32;
#pragma unroll
    for (int j = 0; j < 32; j += 8)
        tile[ty + j][tx] = W[(size_t)(y0 + ty + j) * DD + x0 + tx];
    __syncthreads();
#pragma unroll
    for (int j = 0; j < 32; j += 8)
        Wt[(size_t)(x0 + ty + j) * DD + y0 + tx] = __float2bfloat16(tile[tx][ty + j]);
}

// ---------------- fused LayerNorm + H_pre mixes -> bf16 GEMM inputs ----------------
DEV_INLINE uint32_t packbf2(float a, float b) {
    __nv_bfloat162 t = __floats2bfloat162_rn(a, b);
    return *reinterpret_cast<uint32_t*>(&t);
}
__global__ void __launch_bounds__(256) pre_kernel(const float* __restrict__ x,
                                                  const float* __restrict__ gamma,
                                                  const float* __restrict__ beta) {
    __shared__ float sx[DD];
    __shared__ float sg[DD];
    __shared__ float sb[DD];
    __shared__ float sred[18];
    const int tid = threadIdx.x;
    const float* xr = x + (size_t)blockIdx.x * DD;
    float s1 = 0.f, s2 = 0.f;
#pragma unroll
    for (int j = 0; j < 2; j++) {
        int i4 = tid * 2 + j;
        float4 v = ((const float4*)xr)[i4];
        ((float4*)sx)[i4] = v;
        ((float4*)sg)[i4] = ((const float4*)gamma)[i4];
        ((float4*)sb)[i4] = ((const float4*)beta)[i4];
        s1 += v.x + v.y + v.z + v.w;
        s2 += v.x*v.x + v.y*v.y + v.z*v.z + v.w*v.w;
    }
#pragma unroll
    for (int off = 16; off > 0; off >>= 1) {
        s1 += __shfl_xor_sync(0xffffffffu, s1, off);
        s2 += __shfl_xor_sync(0xffffffffu, s2, off);
    }
    if ((tid & 31) == 0) { sred[tid >> 5] = s1; sred[8 + (tid >> 5)] = s2; }
    __syncthreads();
    if (tid == 0) {
        float a = 0.f, b = 0.f;
        for (int w = 0; w < 8; w++) { a += sred[w]; b += sred[8 + w]; }
        float mu = a * (1.f / DD);
        float var = b * (1.f / DD) - mu * mu;
        sred[16] = mu;
        sred[17] = rsqrtf(var + 1e-5f);
    }
    __syncthreads();
    const float mu = sred[16], rstd = sred[17];

    const int q0 = tid * 8;
    const int t  = q0 >> 9;
    const int dp = q0 & 511;
    float wa[4], wh[4];
#pragma unroll
    for (int s = 0; s < 4; s++) { wa[s] = g_sm.pre_a[s][t]; wh[s] = g_sm.pre_h[s][t]; }

    float va[8], vh[8];
#pragma unroll
    for (int j = 0; j < 8; j++) {
        int d = dp + j;
        float aa = 0.f, hh = 0.f;
#pragma unroll
        for (int s = 0; s < 4; s++) {
            int i = s * SD + d;
            float xv = sx[i];
            float nv = (xv - mu) * rstd * sg[i] + sb[i];
            aa += wa[s] * nv;
            hh += wh[s] * xv;
        }
        va[j] = aa; vh[j] = hh;
    }
    uint4 ua, uh;
    ua.x = packbf2(va[0], va[1]); ua.y = packbf2(va[2], va[3]);
    ua.z = packbf2(va[4], va[5]); ua.w = packbf2(va[6], va[7]);
    uh.x = packbf2(vh[0], vh[1]); uh.y = packbf2(vh[2], vh[3]);
    uh.z = packbf2(vh[4], vh[5]); uh.w = packbf2(vh[6], vh[7]);
    size_t ob = (size_t)blockIdx.x * DD + q0;
    *(uint4*)(g_Aa + ob) = ua;
    *(uint4*)(g_Ah + ob) = uh;
}

// ---------------- bf16 mma.sync GEMM: C[16384,2048] = A @ W ----------------
// CTA tile 128x128, BK=64, 3-stage cp.async pipeline, 8 warps (4m x 2n),
// warp tile 32x64, m16n8k16 HMMA with fp32 accumulation.
__global__ void __launch_bounds__(256, 1) gemm_kernel() {
    extern __shared__ __align__(128) char dsm[];

    const int tid  = threadIdx.x;
    const int wid  = tid >> 5;
    const int lane = tid & 31;
    const int nb = blockIdx.x, mbk = blockIdx.y, gz = blockIdx.z;
    const __nv_bfloat16* __restrict__ A  = gz ? g_Ah  : g_Aa;
    const __nv_bfloat16* __restrict__ Bt = gz ? g_Wth : g_Wta;
    float* __restrict__ C = gz ? g_Ch : g_Ca;
    const int m0 = mbk * 128, n0 = nb * 128;

    const uint32_t smem_base = smem_u32(dsm);

    // cp.async per-thread tile-load offsets: thread handles 4 x 16B for A, 4 x 16B for B
    const int lrow = tid >> 3;       // 0..31  (x4 = rows 0..127 via +32 step)
    const int lcol = tid & 7;        // 0..7   (16B column)

    // warp layout
    const int wm = wid & 3;          // 0..3  -> 32 m-rows each
    const int wn = wid >> 2;         // 0..1  -> 64 n-cols each
    const int mwarp = wm * 32, nwarp = wn * 64;

    // ldmatrix per-lane addressing pieces
    const int lrow16 = lane & 15;          // row within 16-block
    const int lkhalf = (lane >> 4) * 16;   // byte offset of k half (8 elems * 2B)

    float acc[2][8][4];
#pragma unroll
    for (int i = 0; i < 2; i++)
#pragma unroll
        for (int j = 0; j < 8; j++)
#pragma unroll
            for (int q = 0; q < 4; q++) acc[i][j][q] = 0.f;

    auto load_stage = [&](int stage, int chunk) {
        const uint32_t st = smem_base + stage * STAGE_BYTES;
        const int kbase = chunk * BK;
        const __nv_bfloat16* Ap = A  + (size_t)(m0 + lrow) * DD + kbase + lcol * 8;
        const __nv_bfloat16* Bp = Bt + (size_t)(n0 + lrow) * DD + kbase + lcol * 8;
#pragma unroll
        for (int j = 0; j < 4; j++) {
            int r = lrow + 32 * j;
            cp_async16(st + SW128(r * 128 + lcol * 16), Ap + (size_t)(32 * j) * DD);
            cp_async16(st + 16384 + SW128(r * 128 + lcol * 16), Bp + (size_t)(32 * j) * DD);
        }
        cp_commit();
    };

    load_stage(0, 0);
    load_stage(1, 1);

    for (int c = 0; c < NK_CHUNKS; c++) {
        if (c < NK_CHUNKS - 2) cp_wait<1>(); else cp_wait<0>();
        __syncthreads();
        if (c + 2 < NK_CHUNKS) load_stage((c + 2) % STAGES, c + 2);

        const uint32_t stA = smem_base + (c % STAGES) * STAGE_BYTES;
        const uint32_t stB = stA + 16384;
#pragma unroll
        for (int ks = 0; ks < 4; ks++) {
            const int kb = ks * 32 + lkhalf;   // byte offset along k
            uint32_t af[2][4], bf[4][4];
#pragma unroll
            for (int i = 0; i < 2; i++)
                ldm_x4(af[i], stA + SW128((mwarp + i * 16 + lrow16) * 128 + kb));
#pragma unroll
            for (int j = 0; j < 4; j++)
                ldm_x4(bf[j], stB + SW128((nwarp + j * 16 + lrow16) * 128 + kb));
#pragma unroll
            for (int i = 0; i < 2; i++)
#pragma unroll
                for (int j = 0; j < 4; j++) {
                    mma16816(acc[i][j * 2 + 0], af[i], bf[j][0], bf[j][2]);
                    mma16816(acc[i][j * 2 + 1], af[i], bf[j][1], bf[j][3]);
                }
        }
    }

    // epilogue: direct fp32 stores (float2 per accum half)
    const int erow = lane >> 2;
    const int ecol = (lane & 3) * 2;
#pragma unroll
    for (int i = 0; i < 2; i++) {
#pragma unroll
        for (int j = 0; j < 8; j++) {
            int m = m0 + mwarp + i * 16 + erow;
            int n = n0 + nwarp + j * 8 + ecol;
            float* p0 = C + (size_t)m * DD + n;
            *(float2*)p0 = make_float2(acc[i][j][0], acc[i][j][1]);
            *(float2*)(p0 + (size_t)8 * DD) = make_float2(acc[i][j][2], acc[i][j][3]);
        }
    }
}

// ---------------- fused epilogue: residual + post mix + alpha blend ----------------
__global__ void __launch_bounds__(128) final_kernel(const float* __restrict__ x,
                                                    const float* __restrict__ ba,
                                                    const float* __restrict__ bh,
                                                    float* __restrict__ out) {
    const size_t base = (size_t)blockIdx.x * DD;
    const int d0 = threadIdx.x * 4;
    float xv[4][4], ca[4][4], ch[4][4];
#pragma unroll
    for (int s = 0; s < 4; s++) {
        int off = s * SD + d0;
        float4 v  = *(const float4*)(x + base + off);
        float4 c1 = *(const float4*)(g_Ca + base + off);
        float4 c2 = *(const float4*)(g_Ch + base + off);
        float4 b1 = *(const float4*)(ba + off);
        float4 b2 = *(const float4*)(bh + off);
        xv[s][0]=v.x;  xv[s][1]=v.y;  xv[s][2]=v.z;  xv[s][3]=v.w;
        ca[s][0]=c1.x+b1.x; ca[s][1]=c1.y+b1.y; ca[s][2]=c1.z+b1.z; ca[s][3]=c1.w+b1.w;
        ch[s][0]=c2.x+b2.x; ch[s][1]=c2.y+b2.y; ch[s][2]=c2.z+b2.z; ch[s][3]=c2.w+b2.w;
    }
    const float alpha = g_sm.alpha;
    const float beta1 = 1.f - alpha;
#pragma unroll
    for (int t = 0; t < 4; t++) {
        float sca = g_sm.sc_a[t], sch = g_sm.sc_h[t];
        float o[4] = {0.f, 0.f, 0.f, 0.f};
#pragma unroll
        for (int s = 0; s < 4; s++) {
            float wra = alpha * g_sm.res_a[s][t];
            float wrh = beta1 * g_sm.res_h[s][t];
            float wpa = alpha * sca * g_sm.post_a[t][s];
            float wph = beta1 * sch * g_sm.post_h[t][s];
#pragma unroll
            for (int k = 0; k < 4; k++)
                o[k] += (wra + wrh) * xv[s][k] + wpa * ca[s][k] + wph * ch[s][k];
        }
        float4 ov; ov.x = o[0]; ov.y = o[1]; ov.z = o[2]; ov.w = o[3];
        *(float4*)(out + base + t * SD + d0) = ov;
    }
}

// ---------------- launch ----------------
extern "C" void kernel_launch(void* const* d_in, const int* in_sizes, int n_in,
                              void* d_out, int out_size) {
    const float* x     = (const float*)d_in[0];
    const float* g     = (const float*)d_in[1];
    const float* b     = (const float*)d_in[2];
    const float* Wa    = (const float*)d_in[3];
    const float* ba    = (const float*)d_in[4];
    const float* Wh    = (const float*)d_in[5];
    const float* bh    = (const float*)d_in[6];
    const float* pre_a = (const float*)d_in[7];
    const float* pre_h = (const float*)d_in[8];
    const float* res_a = (const float*)d_in[9];
    const float* post_a= (const float*)d_in[10];
    const float* sc_a  = (const float*)d_in[11];
    const float* res_h = (const float*)d_in[12];
    const float* post_h= (const float*)d_in[13];
    const float* sc_h  = (const float*)d_in[14];
    const float* cm    = (const float*)d_in[15];
    float* out = (float*)d_out;

    cudaFuncSetAttribute(gemm_kernel, cudaFuncAttributeMaxDynamicSharedMemorySize, DYN_SMEM);

    small_kernel<<<1, 32>>>(pre_a, pre_h, res_a, post_a, sc_a, res_h, post_h, sc_h, cm);
    wtrans_kernel<<<dim3(64, 64, 2), dim3(32, 8)>>>(Wa, Wh);
    pre_kernel<<<MROWS, 256>>>(x, g, b);
    gemm_kernel<<<dim3(16, 128, 2), 256, DYN_SMEM>>>();
    final_kernel<<<MROWS, 128>>>(x, ba, bh, out);
}

// round 3
// speedup vs baseline: 1.1162x; 1.1162x over previous
#include <cuda_runtime.h>
#include <cuda_bf16.h>
#include <cstdint>

#define DEV_INLINE __device__ __forceinline__

// ---------------- problem sizes (fixed) ----------------
#define DD    2048
#define SD    512
#define MROWS 16384          // B*N = 4*4096
#define BK    64             // K elements per pipeline chunk (bf16)
#define NK_CHUNKS 32         // 2048/64
#define STAGES 3
#define STAGE_BYTES 32768    // A tile 16KB + B tile 16KB
#define DYN_SMEM (STAGES * STAGE_BYTES)

// ---------------- device scratch (static, no allocs) ----------------
__device__ __nv_bfloat16 g_Aa[(size_t)MROWS * DD];
__device__ __nv_bfloat16 g_Ah[(size_t)MROWS * DD];
__device__ __nv_bfloat16 g_Wta[(size_t)DD * DD];
__device__ __nv_bfloat16 g_Wth[(size_t)DD * DD];
__device__ float         g_Ca[(size_t)MROWS * DD];
__device__ float         g_Ch[(size_t)MROWS * DD];

struct SmallMats {
    float pre_a[4][4], pre_h[4][4];
    float res_a[4][4], res_h[4][4];
    float post_a[4][4], post_h[4][4];
    float sc_a[4], sc_h[4];
    float alpha;
};
__device__ SmallMats g_sm;

// ---------------- PTX helpers (base ISA only: sm_80+) ----------------
DEV_INLINE uint32_t smem_u32(const void* p) {
    uint32_t a;
    asm("{ .reg .u64 t; cvta.to.shared.u64 t, %1; cvt.u32.u64 %0, t; }" : "=r"(a) : "l"(p));
    return a;
}
#define SW128(o) ((o) ^ ((((uint32_t)(o)) >> 3) & 0x70u))

DEV_INLINE void cp_async16(uint32_t dst, const void* src) {
    asm volatile("cp.async.cg.shared.global [%0], [%1], 16;" :: "r"(dst), "l"(src));
}
DEV_INLINE void cp_commit() { asm volatile("cp.async.commit_group;" ::: "memory"); }
template<int N> DEV_INLINE void cp_wait() {
    asm volatile("cp.async.wait_group %0;" :: "n"(N) : "memory");
}
DEV_INLINE void ldm_x4(uint32_t* r, uint32_t addr) {
    asm volatile("ldmatrix.sync.aligned.m8n8.x4.shared.b16 {%0,%1,%2,%3}, [%4];"
                 : "=r"(r[0]), "=r"(r[1]), "=r"(r[2]), "=r"(r[3]) : "r"(addr));
}
DEV_INLINE void mma16816(float* d, const uint32_t* a, uint32_t b0, uint32_t b1) {
    asm volatile(
        "mma.sync.aligned.m16n8k16.row.col.f32.bf16.bf16.f32 "
        "{%0,%1,%2,%3}, {%4,%5,%6,%7}, {%8,%9}, {%0,%1,%2,%3};"
        : "+f"(d[0]), "+f"(d[1]), "+f"(d[2]), "+f"(d[3])
        : "r"(a[0]), "r"(a[1]), "r"(a[2]), "r"(a[3]), "r"(b0), "r"(b1));
}

// ---------------- small 4x4 matrix kernel ----------------
DEV_INLINE void softmax4(const float* L, float O[4][4]) {
    for (int s = 0; s < 4; s++) {
        float mx = L[s*4];
        for (int t = 1; t < 4; t++) mx = fmaxf(mx, L[s*4+t]);
        float sum = 0.f, e[4];
        for (int t = 0; t < 4; t++) { e[t] = expf(L[s*4+t] - mx); sum += e[t]; }
        float inv = 1.f / sum;
        for (int t = 0; t < 4; t++) O[s][t] = e[t] * inv;
    }
}
DEV_INLINE void sinkhorn4(const float* L, float P[4][4]) {
    float mx = L[0];
    for (int i = 1; i < 16; i++) mx = fmaxf(mx, L[i]);
    for (int s = 0; s < 4; s++)
        for (int t = 0; t < 4; t++) P[s][t] = expf(L[s*4+t] - mx);
    for (int it = 0; it < 20; it++) {
        for (int s = 0; s < 4; s++) {
            float rs = P[s][0] + P[s][1] + P[s][2] + P[s][3];
            float inv = 1.f / (rs + 1e-8f);
            for (int t = 0; t < 4; t++) P[s][t] *= inv;
        }
        for (int t = 0; t < 4; t++) {
            float cs = P[0][t] + P[1][t] + P[2][t] + P[3][t];
            float inv = 1.f / (cs + 1e-8f);
            for (int s = 0; s < 4; s++) P[s][t] *= inv;
        }
    }
}
__global__ void small_kernel(const float* pa, const float* ph,
                             const float* ra, const float* po_a, const float* sa,
                             const float* rh, const float* po_h, const float* sh,
                             const float* cm) {
    if (threadIdx.x != 0) return;
    softmax4(pa,   g_sm.pre_a);
    softmax4(ph,   g_sm.pre_h);
    softmax4(po_a, g_sm.post_a);
    softmax4(po_h, g_sm.post_h);
    sinkhorn4(ra,  g_sm.res_a);
    sinkhorn4(rh,  g_sm.res_h);
    for (int t = 0; t < 4; t++) { g_sm.sc_a[t] = sa[t]; g_sm.sc_h[t] = sh[t]; }
    g_sm.alpha = 1.f / (1.f + expf(-cm[0]));
}

// ---------------- W transpose + bf16 quantize -> Wt[n][k] ----------------
__global__ void wtrans_kernel(const float* __restrict__ Wa, const float* __restrict__ Wh) {
    __shared__ float tile[32][33];
    const float* W = blockIdx.z ? Wh : Wa;
    __nv_bfloat16* Wt = blockIdx.z ? g_Wth : g_Wta;
    int tx = threadIdx.x, ty = threadIdx.y;
    int x0 = blockIdx.x * 32, y0 = blockIdx.y * 32;
#pragma unroll
    for (int j = 0; j < 32; j += 8)
        tile[ty + j][tx] = W[(size_t)(y0 + ty + j) * DD + x0 + tx];
    __syncthreads();
#pragma unroll
    for (int j = 0; j < 32; j += 8)
        Wt[(size_t)(x0 + ty + j) * DD + y0 + tx] = __float2bfloat16(tile[tx][ty + j]);
}

// ---------------- fused LayerNorm + H_pre mixes -> bf16 GEMM inputs ----------------
DEV_INLINE uint32_t packbf2(float a, float b) {
    __nv_bfloat162 t = __floats2bfloat162_rn(a, b);
    return *reinterpret_cast<uint32_t*>(&t);
}
__global__ void __launch_bounds__(256) pre_kernel(const float* __restrict__ x,
                                                  const float* __restrict__ gamma,
                                                  const float* __restrict__ beta) {
    __shared__ float sx[DD];
    __shared__ float sg[DD];
    __shared__ float sb[DD];
    __shared__ float sred[18];
    const int tid = threadIdx.x;
    const float* xr = x + (size_t)blockIdx.x * DD;
    float s1 = 0.f, s2 = 0.f;
#pragma unroll
    for (int j = 0; j < 2; j++) {
        int i4 = tid * 2 + j;
        float4 v = ((const float4*)xr)[i4];
        ((float4*)sx)[i4] = v;
        ((float4*)sg)[i4] = ((const float4*)gamma)[i4];
        ((float4*)sb)[i4] = ((const float4*)beta)[i4];
        s1 += v.x + v.y + v.z + v.w;
        s2 += v.x*v.x + v.y*v.y + v.z*v.z + v.w*v.w;
    }
#pragma unroll
    for (int off = 16; off > 0; off >>= 1) {
        s1 += __shfl_xor_sync(0xffffffffu, s1, off);
        s2 += __shfl_xor_sync(0xffffffffu, s2, off);
    }
    if ((tid & 31) == 0) { sred[tid >> 5] = s1; sred[8 + (tid >> 5)] = s2; }
    __syncthreads();
    if (tid == 0) {
        float a = 0.f, b = 0.f;
        for (int w = 0; w < 8; w++) { a += sred[w]; b += sred[8 + w]; }
        float mu = a * (1.f / DD);
        float var = b * (1.f / DD) - mu * mu;
        sred[16] = mu;
        sred[17] = rsqrtf(var + 1e-5f);
    }
    __syncthreads();
    const float mu = sred[16], rstd = sred[17];

    const int q0 = tid * 8;
    const int t  = q0 >> 9;
    const int dp = q0 & 511;
    float wa[4], wh[4];
#pragma unroll
    for (int s = 0; s < 4; s++) { wa[s] = g_sm.pre_a[s][t]; wh[s] = g_sm.pre_h[s][t]; }

    float va[8], vh[8];
#pragma unroll
    for (int j = 0; j < 8; j++) {
        int d = dp + j;
        float aa = 0.f, hh = 0.f;
#pragma unroll
        for (int s = 0; s < 4; s++) {
            int i = s * SD + d;
            float xv = sx[i];
            float nv = (xv - mu) * rstd * sg[i] + sb[i];
            aa += wa[s] * nv;
            hh += wh[s] * xv;
        }
        va[j] = aa; vh[j] = hh;
    }
    uint4 ua, uh;
    ua.x = packbf2(va[0], va[1]); ua.y = packbf2(va[2], va[3]);
    ua.z = packbf2(va[4], va[5]); ua.w = packbf2(va[6], va[7]);
    uh.x = packbf2(vh[0], vh[1]); uh.y = packbf2(vh[2], vh[3]);
    uh.z = packbf2(vh[4], vh[5]); uh.w = packbf2(vh[6], vh[7]);
    size_t ob = (size_t)blockIdx.x * DD + q0;
    *(uint4*)(g_Aa + ob) = ua;
    *(uint4*)(g_Ah + ob) = uh;
}

// ---------------- bf16 mma.sync GEMM: C[16384,2048] = A @ W ----------------
// CTA tile 128x128, BK=64, 3-stage cp.async pipeline, 8 warps (4m x 2n),
// warp tile 32x64, m16n8k16 HMMA with fp32 accumulation.
// __launch_bounds__(256, 2): cap regs at 128 so 2 CTAs co-reside per SM
// (16 warps -> 4/SMSP) to hide ldmatrix + barrier latency.
__global__ void __launch_bounds__(256, 2) gemm_kernel() {
    extern __shared__ __align__(128) char dsm[];

    const int tid  = threadIdx.x;
    const int wid  = tid >> 5;
    const int lane = tid & 31;
    const int nb = blockIdx.x, mbk = blockIdx.y, gz = blockIdx.z;
    const __nv_bfloat16* __restrict__ A  = gz ? g_Ah  : g_Aa;
    const __nv_bfloat16* __restrict__ Bt = gz ? g_Wth : g_Wta;
    float* __restrict__ C = gz ? g_Ch : g_Ca;
    const int m0 = mbk * 128, n0 = nb * 128;

    const uint32_t smem_base = smem_u32(dsm);

    // cp.async per-thread tile-load offsets: thread handles 4 x 16B for A, 4 x 16B for B
    const int lrow = tid >> 3;       // 0..31  (x4 = rows 0..127 via +32 step)
    const int lcol = tid & 7;        // 0..7   (16B column)

    // warp layout
    const int wm = wid & 3;          // 0..3  -> 32 m-rows each
    const int wn = wid >> 2;         // 0..1  -> 64 n-cols each
    const int mwarp = wm * 32, nwarp = wn * 64;

    // ldmatrix per-lane addressing pieces
    const int lrow16 = lane & 15;          // row within 16-block
    const int lkhalf = (lane >> 4) * 16;   // byte offset of k half (8 elems * 2B)

    float acc[2][8][4];
#pragma unroll
    for (int i = 0; i < 2; i++)
#pragma unroll
        for (int j = 0; j < 8; j++)
#pragma unroll
            for (int q = 0; q < 4; q++) acc[i][j][q] = 0.f;

    auto load_stage = [&](int stage, int chunk) {
        const uint32_t st = smem_base + stage * STAGE_BYTES;
        const int kbase = chunk * BK;
        const __nv_bfloat16* Ap = A  + (size_t)(m0 + lrow) * DD + kbase + lcol * 8;
        const __nv_bfloat16* Bp = Bt + (size_t)(n0 + lrow) * DD + kbase + lcol * 8;
#pragma unroll
        for (int j = 0; j < 4; j++) {
            int r = lrow + 32 * j;
            cp_async16(st + SW128(r * 128 + lcol * 16), Ap + (size_t)(32 * j) * DD);
            cp_async16(st + 16384 + SW128(r * 128 + lcol * 16), Bp + (size_t)(32 * j) * DD);
        }
        cp_commit();
    };

    load_stage(0, 0);
    load_stage(1, 1);

    for (int c = 0; c < NK_CHUNKS; c++) {
        if (c < NK_CHUNKS - 2) cp_wait<1>(); else cp_wait<0>();
        __syncthreads();
        if (c + 2 < NK_CHUNKS) load_stage((c + 2) % STAGES, c + 2);

        const uint32_t stA = smem_base + (c % STAGES) * STAGE_BYTES;
        const uint32_t stB = stA + 16384;
#pragma unroll
        for (int ks = 0; ks < 4; ks++) {
            const int kb = ks * 32 + lkhalf;   // byte offset along k
            uint32_t af[2][4], bf[4][4];
#pragma unroll
            for (int i = 0; i < 2; i++)
                ldm_x4(af[i], stA + SW128((mwarp + i * 16 + lrow16) * 128 + kb));
#pragma unroll
            for (int j = 0; j < 4; j++)
                ldm_x4(bf[j], stB + SW128((nwarp + j * 16 + lrow16) * 128 + kb));
#pragma unroll
            for (int i = 0; i < 2; i++)
#pragma unroll
                for (int j = 0; j < 4; j++) {
                    mma16816(acc[i][j * 2 + 0], af[i], bf[j][0], bf[j][2]);
                    mma16816(acc[i][j * 2 + 1], af[i], bf[j][1], bf[j][3]);
                }
        }
    }

    // epilogue: direct fp32 stores (float2 per accum half)
    const int erow = lane >> 2;
    const int ecol = (lane & 3) * 2;
#pragma unroll
    for (int i = 0; i < 2; i++) {
#pragma unroll
        for (int j = 0; j < 8; j++) {
            int m = m0 + mwarp + i * 16 + erow;
            int n = n0 + nwarp + j * 8 + ecol;
            float* p0 = C + (size_t)m * DD + n;
            *(float2*)p0 = make_float2(acc[i][j][0], acc[i][j][1]);
            *(float2*)(p0 + (size_t)8 * DD) = make_float2(acc[i][j][2], acc[i][j][3]);
        }
    }
}

// ---------------- fused epilogue: residual + post mix + alpha blend ----------------
__global__ void __launch_bounds__(128) final_kernel(const float* __restrict__ x,
                                                    const float* __restrict__ ba,
                                                    const float* __restrict__ bh,
                                                    float* __restrict__ out) {
    const size_t base = (size_t)blockIdx.x * DD;
    const int d0 = threadIdx.x * 4;
    float xv[4][4], ca[4][4], ch[4][4];
#pragma unroll
    for (int s = 0; s < 4; s++) {
        int off = s * SD + d0;
        float4 v  = *(const float4*)(x + base + off);
        float4 c1 = *(const float4*)(g_Ca + base + off);
        float4 c2 = *(const float4*)(g_Ch + base + off);
        float4 b1 = *(const float4*)(ba + off);
        float4 b2 = *(const float4*)(bh + off);
        xv[s][0]=v.x;  xv[s][1]=v.y;  xv[s][2]=v.z;  xv[s][3]=v.w;
        ca[s][0]=c1.x+b1.x; ca[s][1]=c1.y+b1.y; ca[s][2]=c1.z+b1.z; ca[s][3]=c1.w+b1.w;
        ch[s][0]=c2.x+b2.x; ch[s][1]=c2.y+b2.y; ch[s][2]=c2.z+b2.z; ch[s][3]=c2.w+b2.w;
    }
    const float alpha = g_sm.alpha;
    const float beta1 = 1.f - alpha;
#pragma unroll
    for (int t = 0; t < 4; t++) {
        float sca = g_sm.sc_a[t], sch = g_sm.sc_h[t];
        float o[4] = {0.f, 0.f, 0.f, 0.f};
#pragma unroll
        for (int s = 0; s < 4; s++) {
            float wra = alpha * g_sm.res_a[s][t];
            float wrh = beta1 * g_sm.res_h[s][t];
            float wpa = alpha * sca * g_sm.post_a[t][s];
            float wph = beta1 * sch * g_sm.post_h[t][s];
#pragma unroll
            for (int k = 0; k < 4; k++)
                o[k] += (wra + wrh) * xv[s][k] + wpa * ca[s][k] + wph * ch[s][k];
        }
        float4 ov; ov.x = o[0]; ov.y = o[1]; ov.z = o[2]; ov.w = o[3];
        *(float4*)(out + base + t * SD + d0) = ov;
    }
}

// ---------------- launch ----------------
extern "C" void kernel_launch(void* const* d_in, const int* in_sizes, int n_in,
                              void* d_out, int out_size) {
    const float* x     = (const float*)d_in[0];
    const float* g     = (const float*)d_in[1];
    const float* b     = (const float*)d_in[2];
    const float* Wa    = (const float*)d_in[3];
    const float* ba    = (const float*)d_in[4];
    const float* Wh    = (const float*)d_in[5];
    const float* bh    = (const float*)d_in[6];
    const float* pre_a = (const float*)d_in[7];
    const float* pre_h = (const float*)d_in[8];
    const float* res_a = (const float*)d_in[9];
    const float* post_a= (const float*)d_in[10];
    const float* sc_a  = (const float*)d_in[11];
    const float* res_h = (const float*)d_in[12];
    const float* post_h= (const float*)d_in[13];
    const float* sc_h  = (const float*)d_in[14];
    const float* cm    = (const float*)d_in[15];
    float* out = (float*)d_out;

    cudaFuncSetAttribute(gemm_kernel, cudaFuncAttributeMaxDynamicSharedMemorySize, DYN_SMEM);

    small_kernel<<<1, 32>>>(pre_a, pre_h, res_a, post_a, sc_a, res_h, post_h, sc_h, cm);
    wtrans_kernel<<<dim3(64, 64, 2), dim3(32, 8)>>>(Wa, Wh);
    pre_kernel<<<MROWS, 256>>>(x, g, b);
    gemm_kernel<<<dim3(16, 128, 2), 256, DYN_SMEM>>>();
    final_kernel<<<MROWS, 128>>>(x, ba, bh, out);
}

// round 4
// speedup vs baseline: 1.1802x; 1.0573x over previous
#include <cuda_runtime.h>
#include <cuda_bf16.h>
#include <cstdint>

#define DEV_INLINE __device__ __forceinline__

// ---------------- problem sizes (fixed) ----------------
#define DD    2048
#define SD    512
#define MROWS 16384          // B*N = 4*4096
#define KTOT  4096           // concatenated K (attn 2048 | hyb 2048)
#define BK    64             // K elements per pipeline chunk (bf16)
#define NK_CHUNKS 64         // 4096/64
#define STAGES 3
#define STAGE_BYTES 32768    // A tile 16KB + B tile 16KB
#define DYN_SMEM (STAGES * STAGE_BYTES)

// ---------------- device scratch (static, no allocs) ----------------
__device__ __nv_bfloat16 g_Aa[(size_t)MROWS * DD];
__device__ __nv_bfloat16 g_Ah[(size_t)MROWS * DD];
__device__ __nv_bfloat16 g_Wc[(size_t)DD * KTOT];   // permuted combined weights [p][k]
__device__ float         g_bias[DD];                // permuted combined bias

struct SmallMats {
    float pre_a[4][4], pre_h[4][4];
    float ca_mix[4][4], ch_mix[4][4];   // alpha*sc*post (t,s)
    float Rw[4][4];                     // combined residual mix (s,t)
    float alpha;
};
__device__ SmallMats g_sm;

// ---------------- PTX helpers (base ISA only: sm_80+) ----------------
DEV_INLINE uint32_t smem_u32(const void* p) {
    uint32_t a;
    asm("{ .reg .u64 t; cvta.to.shared.u64 t, %1; cvt.u32.u64 %0, t; }" : "=r"(a) : "l"(p));
    return a;
}
#define SW128(o) ((o) ^ ((((uint32_t)(o)) >> 3) & 0x70u))

DEV_INLINE void cp_async16(uint32_t dst, const void* src) {
    asm volatile("cp.async.cg.shared.global [%0], [%1], 16;" :: "r"(dst), "l"(src));
}
DEV_INLINE void cp_commit() { asm volatile("cp.async.commit_group;" ::: "memory"); }
template<int N> DEV_INLINE void cp_wait() {
    asm volatile("cp.async.wait_group %0;" :: "n"(N) : "memory");
}
DEV_INLINE void ldm_x4(uint32_t* r, uint32_t addr) {
    asm volatile("ldmatrix.sync.aligned.m8n8.x4.shared.b16 {%0,%1,%2,%3}, [%4];"
                 : "=r"(r[0]), "=r"(r[1]), "=r"(r[2]), "=r"(r[3]) : "r"(addr));
}
DEV_INLINE void mma16816(float* d, const uint32_t* a, uint32_t b0, uint32_t b1) {
    asm volatile(
        "mma.sync.aligned.m16n8k16.row.col.f32.bf16.bf16.f32 "
        "{%0,%1,%2,%3}, {%4,%5,%6,%7}, {%8,%9}, {%0,%1,%2,%3};"
        : "+f"(d[0]), "+f"(d[1]), "+f"(d[2]), "+f"(d[3])
        : "r"(a[0]), "r"(a[1]), "r"(a[2]), "r"(a[3]), "r"(b0), "r"(b1));
}

// ---------------- small 4x4 matrix kernel ----------------
DEV_INLINE void softmax4(const float* L, float O[4][4]) {
    for (int s = 0; s < 4; s++) {
        float mx = L[s*4];
        for (int t = 1; t < 4; t++) mx = fmaxf(mx, L[s*4+t]);
        float sum = 0.f, e[4];
        for (int t = 0; t < 4; t++) { e[t] = expf(L[s*4+t] - mx); sum += e[t]; }
        float inv = 1.f / sum;
        for (int t = 0; t < 4; t++) O[s][t] = e[t] * inv;
    }
}
DEV_INLINE void sinkhorn4(const float* L, float P[4][4]) {
    float mx = L[0];
    for (int i = 1; i < 16; i++) mx = fmaxf(mx, L[i]);
    for (int s = 0; s < 4; s++)
        for (int t = 0; t < 4; t++) P[s][t] = expf(L[s*4+t] - mx);
    for (int it = 0; it < 20; it++) {
        for (int s = 0; s < 4; s++) {
            float rs = P[s][0] + P[s][1] + P[s][2] + P[s][3];
            float inv = 1.f / (rs + 1e-8f);
            for (int t = 0; t < 4; t++) P[s][t] *= inv;
        }
        for (int t = 0; t < 4; t++) {
            float cs = P[0][t] + P[1][t] + P[2][t] + P[3][t];
            float inv = 1.f / (cs + 1e-8f);
            for (int s = 0; s < 4; s++) P[s][t] *= inv;
        }
    }
}
__global__ void small_kernel(const float* pa, const float* ph,
                             const float* ra, const float* po_a, const float* sa,
                             const float* rh, const float* po_h, const float* sh,
                             const float* cm) {
    if (threadIdx.x != 0) return;
    float post_a[4][4], post_h[4][4], res_a[4][4], res_h[4][4];
    softmax4(pa,   g_sm.pre_a);
    softmax4(ph,   g_sm.pre_h);
    softmax4(po_a, post_a);
    softmax4(po_h, post_h);
    sinkhorn4(ra,  res_a);
    sinkhorn4(rh,  res_h);
    float alpha = 1.f / (1.f + expf(-cm[0]));
    g_sm.alpha = alpha;
    float beta = 1.f - alpha;
    for (int t = 0; t < 4; t++)
        for (int s = 0; s < 4; s++) {
            g_sm.ca_mix[t][s] = alpha * sa[t] * post_a[t][s];
            g_sm.ch_mix[t][s] = beta  * sh[t] * post_h[t][s];
            g_sm.Rw[s][t]     = alpha * res_a[s][t] + beta * res_h[s][t];
        }
}

// ---------------- combined permuted bias ----------------
// permutation: p = (dd>>5)*128 + t*32 + (dd&31), n = t*512 + dd
__global__ void bias_kernel(const float* __restrict__ ba, const float* __restrict__ bh) {
    int p = blockIdx.x * 256 + threadIdx.x;
    int t = (p >> 5) & 3;
    int dd = ((p >> 7) << 5) + (p & 31);
    float v = 0.f;
#pragma unroll
    for (int s = 0; s < 4; s++)
        v += g_sm.ca_mix[t][s] * ba[s * SD + dd] + g_sm.ch_mix[t][s] * bh[s * SD + dd];
    g_bias[p] = v;
}

// ---------------- W transpose + post-mix fold + bf16 quantize ----------------
// g_Wc[p][z*2048+k] = sum_s c_z[t][s] * W_z[k][s*512+dd],  p as above.
__global__ void wtrans_kernel(const float* __restrict__ Wa, const float* __restrict__ Wh) {
    __shared__ float t4[4][32][33];
    const int z = blockIdx.z;
    const float* W = z ? Wh : Wa;
    const int k0 = blockIdx.x * 32;
    const int p0 = blockIdx.y * 32;
    const int t  = (p0 >> 5) & 3;
    const int dd0 = ((p0 >> 7) << 5);
    const int tx = threadIdx.x, ty = threadIdx.y;
#pragma unroll
    for (int s = 0; s < 4; s++)
#pragma unroll
        for (int j = 0; j < 32; j += 8)
            t4[s][ty + j][tx] = W[(size_t)(k0 + ty + j) * DD + s * SD + dd0 + tx];
    __syncthreads();
    float c[4];
#pragma unroll
    for (int s = 0; s < 4; s++)
        c[s] = z ? g_sm.ch_mix[t][s] : g_sm.ca_mix[t][s];
#pragma unroll
    for (int j = 0; j < 32; j += 8) {
        int r = ty + j;
        float v = 0.f;
#pragma unroll
        for (int s = 0; s < 4; s++) v += c[s] * t4[s][tx][r];
        g_Wc[(size_t)(p0 + r) * KTOT + z * DD + k0 + tx] = __float2bfloat16(v);
    }
}

// ---------------- fused LayerNorm + H_pre mixes -> bf16 GEMM inputs ----------------
DEV_INLINE uint32_t packbf2(float a, float b) {
    __nv_bfloat162 t = __floats2bfloat162_rn(a, b);
    return *reinterpret_cast<uint32_t*>(&t);
}
__global__ void __launch_bounds__(256) pre_kernel(const float* __restrict__ x,
                                                  const float* __restrict__ gamma,
                                                  const float* __restrict__ beta) {
    __shared__ float sx[DD];
    __shared__ float sg[DD];
    __shared__ float sb[DD];
    __shared__ float sred[18];
    const int tid = threadIdx.x;
    const float* xr = x + (size_t)blockIdx.x * DD;
    float s1 = 0.f, s2 = 0.f;
#pragma unroll
    for (int j = 0; j < 2; j++) {
        int i4 = tid * 2 + j;
        float4 v = ((const float4*)xr)[i4];
        ((float4*)sx)[i4] = v;
        ((float4*)sg)[i4] = ((const float4*)gamma)[i4];
        ((float4*)sb)[i4] = ((const float4*)beta)[i4];
        s1 += v.x + v.y + v.z + v.w;
        s2 += v.x*v.x + v.y*v.y + v.z*v.z + v.w*v.w;
    }
#pragma unroll
    for (int off = 16; off > 0; off >>= 1) {
        s1 += __shfl_xor_sync(0xffffffffu, s1, off);
        s2 += __shfl_xor_sync(0xffffffffu, s2, off);
    }
    if ((tid & 31) == 0) { sred[tid >> 5] = s1; sred[8 + (tid >> 5)] = s2; }
    __syncthreads();
    if (tid == 0) {
        float a = 0.f, b = 0.f;
        for (int w = 0; w < 8; w++) { a += sred[w]; b += sred[8 + w]; }
        float mu = a * (1.f / DD);
        float var = b * (1.f / DD) - mu * mu;
        sred[16] = mu;
        sred[17] = rsqrtf(var + 1e-5f);
    }
    __syncthreads();
    const float mu = sred[16], rstd = sred[17];

    const int q0 = tid * 8;
    const int t  = q0 >> 9;
    const int dp = q0 & 511;
    float wa[4], wh[4];
#pragma unroll
    for (int s = 0; s < 4; s++) { wa[s] = g_sm.pre_a[s][t]; wh[s] = g_sm.pre_h[s][t]; }

    float va[8], vh[8];
#pragma unroll
    for (int j = 0; j < 8; j++) {
        int d = dp + j;
        float aa = 0.f, hh = 0.f;
#pragma unroll
        for (int s = 0; s < 4; s++) {
            int i = s * SD + d;
            float xv = sx[i];
            float nv = (xv - mu) * rstd * sg[i] + sb[i];
            aa += wa[s] * nv;
            hh += wh[s] * xv;
        }
        va[j] = aa; vh[j] = hh;
    }
    uint4 ua, uh;
    ua.x = packbf2(va[0], va[1]); ua.y = packbf2(va[2], va[3]);
    ua.z = packbf2(va[4], va[5]); ua.w = packbf2(va[6], va[7]);
    uh.x = packbf2(vh[0], vh[1]); uh.y = packbf2(vh[2], vh[3]);
    uh.z = packbf2(vh[4], vh[5]); uh.w = packbf2(vh[6], vh[7]);
    size_t ob = (size_t)blockIdx.x * DD + q0;
    *(uint4*)(g_Aa + ob) = ua;
    *(uint4*)(g_Ah + ob) = uh;
}

// ---------------- fused bf16 mma.sync GEMM + final epilogue ----------------
// out[m, t*512+dd] = bias~ + sum_s Rw[s][t]*x[m, s*512+dd] + GEMM(m, p)
// GEMM: [A_a | A_h](16384x4096) @ g_Wc^T, CTA tile 128x128(p), BK=64, 64 chunks,
// 3-stage cp.async, 8 warps (4m x 2n), warp tile 32x64.
__global__ void __launch_bounds__(256, 2) gemm_kernel(const float* __restrict__ x,
                                                      float* __restrict__ out) {
    extern __shared__ __align__(128) char dsm[];

    const int tid  = threadIdx.x;
    const int wid  = tid >> 5;
    const int lane = tid & 31;
    const int nb = blockIdx.x, mbk = blockIdx.y;
    const int m0 = mbk * 128, n0 = nb * 128;
    const int dd0 = nb * 32;

    const uint32_t smem_base = smem_u32(dsm);

    const int lrow = tid >> 3;       // 0..31
    const int lcol = tid & 7;        // 0..7

    const int wm = wid & 3;
    const int wn = wid >> 2;
    const int mwarp = wm * 32, nwarp = wn * 64;

    const int lrow16 = lane & 15;
    const int lkhalf = (lane >> 4) * 16;

    float acc[2][8][4];
#pragma unroll
    for (int i = 0; i < 2; i++)
#pragma unroll
        for (int j = 0; j < 8; j++)
#pragma unroll
            for (int q = 0; q < 4; q++) acc[i][j][q] = 0.f;

    auto load_stage = [&](int stage, int chunk) {
        const uint32_t st = smem_base + stage * STAGE_BYTES;
        const __nv_bfloat16* Ap;
        if (chunk < 32)
            Ap = g_Aa + (size_t)(m0 + lrow) * DD + chunk * BK + lcol * 8;
        else
            Ap = g_Ah + (size_t)(m0 + lrow) * DD + (chunk - 32) * BK + lcol * 8;
        const __nv_bfloat16* Bp = g_Wc + (size_t)(n0 + lrow) * KTOT + chunk * BK + lcol * 8;
#pragma unroll
        for (int j = 0; j < 4; j++) {
            int r = lrow + 32 * j;
            cp_async16(st + SW128(r * 128 + lcol * 16), Ap + (size_t)(32 * j) * DD);
            cp_async16(st + 16384 + SW128(r * 128 + lcol * 16), Bp + (size_t)(32 * j) * KTOT);
        }
        cp_commit();
    };

    load_stage(0, 0);
    load_stage(1, 1);

    for (int c = 0; c < NK_CHUNKS; c++) {
        if (c < NK_CHUNKS - 2) cp_wait<1>(); else cp_wait<0>();
        __syncthreads();
        if (c + 2 < NK_CHUNKS) load_stage((c + 2) % STAGES, c + 2);

        const uint32_t stA = smem_base + (c % STAGES) * STAGE_BYTES;
        const uint32_t stB = stA + 16384;
#pragma unroll
        for (int ks = 0; ks < 4; ks++) {
            const int kb = ks * 32 + lkhalf;
            uint32_t af[2][4], bf[4][4];
#pragma unroll
            for (int i = 0; i < 2; i++)
                ldm_x4(af[i], stA + SW128((mwarp + i * 16 + lrow16) * 128 + kb));
#pragma unroll
            for (int j = 0; j < 4; j++)
                ldm_x4(bf[j], stB + SW128((nwarp + j * 16 + lrow16) * 128 + kb));
#pragma unroll
            for (int i = 0; i < 2; i++)
#pragma unroll
                for (int j = 0; j < 4; j++) {
                    mma16816(acc[i][j * 2 + 0], af[i], bf[j][0], bf[j][2]);
                    mma16816(acc[i][j * 2 + 1], af[i], bf[j][1], bf[j][3]);
                }
        }
    }

    // fused epilogue: out = acc + bias~ + residual-mix of x
    const int erow = lane >> 2;
    const int ecol = (lane & 3) * 2;
#pragma unroll
    for (int j = 0; j < 8; j++) {
        const int colT = nwarp + j * 8 + ecol;      // 0..127 within CTA tile
        const int t  = colT >> 5;                   // output stream
        const int dd = dd0 + (colT & 31);           // within-stream feature idx
        const float2 bv = *(const float2*)(g_bias + n0 + colT);
        float rw[4];
#pragma unroll
        for (int s = 0; s < 4; s++) rw[s] = g_sm.Rw[s][t];
#pragma unroll
        for (int i = 0; i < 2; i++) {
#pragma unroll
            for (int rr = 0; rr < 2; rr++) {
                const int m = m0 + mwarp + i * 16 + erow + rr * 8;
                const float* xr = x + (size_t)m * DD + dd;
                float o0 = acc[i][j][rr * 2 + 0] + bv.x;
                float o1 = acc[i][j][rr * 2 + 1] + bv.y;
#pragma unroll
                for (int s = 0; s < 4; s++) {
                    float2 xv = *(const float2*)(xr + s * SD);
                    o0 += rw[s] * xv.x;
                    o1 += rw[s] * xv.y;
                }
                *(float2*)(out + (size_t)m * DD + t * SD + dd) = make_float2(o0, o1);
            }
        }
    }
}

// ---------------- launch ----------------
extern "C" void kernel_launch(void* const* d_in, const int* in_sizes, int n_in,
                              void* d_out, int out_size) {
    const float* x     = (const float*)d_in[0];
    const float* g     = (const float*)d_in[1];
    const float* b     = (const float*)d_in[2];
    const float* Wa    = (const float*)d_in[3];
    const float* ba    = (const float*)d_in[4];
    const float* Wh    = (const float*)d_in[5];
    const float* bh    = (const float*)d_in[6];
    const float* pre_a = (const float*)d_in[7];
    const float* pre_h = (const float*)d_in[8];
    const float* res_a = (const float*)d_in[9];
    const float* post_a= (const float*)d_in[10];
    const float* sc_a  = (const float*)d_in[11];
    const float* res_h = (const float*)d_in[12];
    const float* post_h= (const float*)d_in[13];
    const float* sc_h  = (const float*)d_in[14];
    const float* cm    = (const float*)d_in[15];
    float* out = (float*)d_out;

    cudaFuncSetAttribute(gemm_kernel, cudaFuncAttributeMaxDynamicSharedMemorySize, DYN_SMEM);

    small_kernel<<<1, 32>>>(pre_a, pre_h, res_a, post_a, sc_a, res_h, post_h, sc_h, cm);
    bias_kernel<<<8, 256>>>(ba, bh);
    wtrans_kernel<<<dim3(64, 64, 2), dim3(32, 8)>>>(Wa, Wh);
    pre_kernel<<<MROWS, 256>>>(x, g, b);
    gemm_kernel<<<dim3(16, 128), 256, DYN_SMEM>>>(x, out);
}

// round 5
// speedup vs baseline: 1.3119x; 1.1117x over previous
#include <cuda_runtime.h>
#include <cuda_bf16.h>
#include <cstdint>

#define DEV_INLINE __device__ __forceinline__

// ---------------- problem sizes (fixed) ----------------
#define DD    2048
#define SD    512
#define MROWS 16384          // B*N = 4*4096
#define KTOT  4096           // concatenated K (attn 2048 | hyb 2048)
#define BK    64             // K elements per pipeline chunk (bf16)
#define NK_CHUNKS 64         // 4096/64
#define STAGES 3
#define STAGE_BYTES 32768    // A tile 16KB + B tile 16KB
#define DYN_SMEM (STAGES * STAGE_BYTES)

// ---------------- device scratch (static, no allocs) ----------------
__device__ __nv_bfloat16 g_Aa[(size_t)MROWS * DD];
__device__ __nv_bfloat16 g_Ah[(size_t)MROWS * DD];
__device__ __nv_bfloat16 g_Wc[(size_t)DD * KTOT];   // permuted combined weights [p][k]
__device__ float         g_bias[DD];                // permuted combined bias

struct SmallMats {
    float pre_a[4][4], pre_h[4][4];
    float ca_mix[4][4], ch_mix[4][4];   // alpha*sc*post (t,s)
    float Rw[4][4];                     // combined residual mix (s,t)
    float alpha;
};
__device__ SmallMats g_sm;

// ---------------- PTX helpers (base ISA only: sm_80+) ----------------
DEV_INLINE uint32_t smem_u32(const void* p) {
    uint32_t a;
    asm("{ .reg .u64 t; cvta.to.shared.u64 t, %1; cvt.u32.u64 %0, t; }" : "=r"(a) : "l"(p));
    return a;
}
#define SW128(o) ((o) ^ ((((uint32_t)(o)) >> 3) & 0x70u))

DEV_INLINE void cp_async16(uint32_t dst, const void* src) {
    asm volatile("cp.async.cg.shared.global [%0], [%1], 16;" :: "r"(dst), "l"(src));
}
DEV_INLINE void cp_commit() { asm volatile("cp.async.commit_group;" ::: "memory"); }
template<int N> DEV_INLINE void cp_wait() {
    asm volatile("cp.async.wait_group %0;" :: "n"(N) : "memory");
}
DEV_INLINE void ldm_x4(uint32_t* r, uint32_t addr) {
    asm volatile("ldmatrix.sync.aligned.m8n8.x4.shared.b16 {%0,%1,%2,%3}, [%4];"
                 : "=r"(r[0]), "=r"(r[1]), "=r"(r[2]), "=r"(r[3]) : "r"(addr));
}
DEV_INLINE void mma16816(float* d, const uint32_t* a, uint32_t b0, uint32_t b1) {
    asm volatile(
        "mma.sync.aligned.m16n8k16.row.col.f32.bf16.bf16.f32 "
        "{%0,%1,%2,%3}, {%4,%5,%6,%7}, {%8,%9}, {%0,%1,%2,%3};"
        : "+f"(d[0]), "+f"(d[1]), "+f"(d[2]), "+f"(d[3])
        : "r"(a[0]), "r"(a[1]), "r"(a[2]), "r"(a[3]), "r"(b0), "r"(b1));
}

// ---------------- small 4x4 matrix kernel ----------------
DEV_INLINE void softmax4(const float* L, float O[4][4]) {
    for (int s = 0; s < 4; s++) {
        float mx = L[s*4];
        for (int t = 1; t < 4; t++) mx = fmaxf(mx, L[s*4+t]);
        float sum = 0.f, e[4];
        for (int t = 0; t < 4; t++) { e[t] = expf(L[s*4+t] - mx); sum += e[t]; }
        float inv = 1.f / sum;
        for (int t = 0; t < 4; t++) O[s][t] = e[t] * inv;
    }
}
DEV_INLINE void sinkhorn4(const float* L, float P[4][4]) {
    float mx = L[0];
    for (int i = 1; i < 16; i++) mx = fmaxf(mx, L[i]);
    for (int s = 0; s < 4; s++)
        for (int t = 0; t < 4; t++) P[s][t] = expf(L[s*4+t] - mx);
    for (int it = 0; it < 20; it++) {
        for (int s = 0; s < 4; s++) {
            float rs = P[s][0] + P[s][1] + P[s][2] + P[s][3];
            float inv = 1.f / (rs + 1e-8f);
            for (int t = 0; t < 4; t++) P[s][t] *= inv;
        }
        for (int t = 0; t < 4; t++) {
            float cs = P[0][t] + P[1][t] + P[2][t] + P[3][t];
            float inv = 1.f / (cs + 1e-8f);
            for (int s = 0; s < 4; s++) P[s][t] *= inv;
        }
    }
}
__global__ void small_kernel(const float* pa, const float* ph,
                             const float* ra, const float* po_a, const float* sa,
                             const float* rh, const float* po_h, const float* sh,
                             const float* cm) {
    if (threadIdx.x != 0) return;
    float post_a[4][4], post_h[4][4], res_a[4][4], res_h[4][4];
    softmax4(pa,   g_sm.pre_a);
    softmax4(ph,   g_sm.pre_h);
    softmax4(po_a, post_a);
    softmax4(po_h, post_h);
    sinkhorn4(ra,  res_a);
    sinkhorn4(rh,  res_h);
    float alpha = 1.f / (1.f + expf(-cm[0]));
    g_sm.alpha = alpha;
    float beta = 1.f - alpha;
    for (int t = 0; t < 4; t++)
        for (int s = 0; s < 4; s++) {
            g_sm.ca_mix[t][s] = alpha * sa[t] * post_a[t][s];
            g_sm.ch_mix[t][s] = beta  * sh[t] * post_h[t][s];
            g_sm.Rw[s][t]     = alpha * res_a[s][t] + beta * res_h[s][t];
        }
}

// ---------------- combined permuted bias ----------------
// permutation: p = (dd>>5)*128 + t*32 + (dd&31), n = t*512 + dd
__global__ void bias_kernel(const float* __restrict__ ba, const float* __restrict__ bh) {
    int p = blockIdx.x * 256 + threadIdx.x;
    int t = (p >> 5) & 3;
    int dd = ((p >> 7) << 5) + (p & 31);
    float v = 0.f;
#pragma unroll
    for (int s = 0; s < 4; s++)
        v += g_sm.ca_mix[t][s] * ba[s * SD + dd] + g_sm.ch_mix[t][s] * bh[s * SD + dd];
    g_bias[p] = v;
}

// ---------------- W transpose + post-mix fold + bf16 quantize ----------------
// g_Wc[p][z*2048+k] = sum_s c_z[t][s] * W_z[k][s*512+dd],  p as above.
__global__ void wtrans_kernel(const float* __restrict__ Wa, const float* __restrict__ Wh) {
    __shared__ float t4[4][32][33];
    const int z = blockIdx.z;
    const float* W = z ? Wh : Wa;
    const int k0 = blockIdx.x * 32;
    const int p0 = blockIdx.y * 32;
    const int t  = (p0 >> 5) & 3;
    const int dd0 = ((p0 >> 7) << 5);
    const int tx = threadIdx.x, ty = threadIdx.y;
#pragma unroll
    for (int s = 0; s < 4; s++)
#pragma unroll
        for (int j = 0; j < 32; j += 8)
            t4[s][ty + j][tx] = W[(size_t)(k0 + ty + j) * DD + s * SD + dd0 + tx];
    __syncthreads();
    float c[4];
#pragma unroll
    for (int s = 0; s < 4; s++)
        c[s] = z ? g_sm.ch_mix[t][s] : g_sm.ca_mix[t][s];
#pragma unroll
    for (int j = 0; j < 32; j += 8) {
        int r = ty + j;
        float v = 0.f;
#pragma unroll
        for (int s = 0; s < 4; s++) v += c[s] * t4[s][tx][r];
        g_Wc[(size_t)(p0 + r) * KTOT + z * DD + k0 + tx] = __float2bfloat16(v);
    }
}

// ---------------- fused LayerNorm + H_pre mixes -> bf16 GEMM inputs ----------------
// Register-resident: each thread owns 2 feature indices (d0 = tid*2) and
// loads the 4 stream values it needs exactly once; no smem data staging.
DEV_INLINE uint32_t packbf2(float a, float b) {
    __nv_bfloat162 t = __floats2bfloat162_rn(a, b);
    return *reinterpret_cast<uint32_t*>(&t);
}
__global__ void __launch_bounds__(256) pre_kernel(const float* __restrict__ x,
                                                  const float* __restrict__ gamma,
                                                  const float* __restrict__ beta) {
    __shared__ float sred[18];
    const int tid = threadIdx.x;
    const float* xr = x + (size_t)blockIdx.x * DD;
    const int d0 = tid * 2;

    float2 xv[4];
    float s1 = 0.f, s2 = 0.f;
#pragma unroll
    for (int s = 0; s < 4; s++) {
        xv[s] = *(const float2*)(xr + s * SD + d0);
        s1 += xv[s].x + xv[s].y;
        s2 += xv[s].x * xv[s].x + xv[s].y * xv[s].y;
    }
#pragma unroll
    for (int off = 16; off > 0; off >>= 1) {
        s1 += __shfl_xor_sync(0xffffffffu, s1, off);
        s2 += __shfl_xor_sync(0xffffffffu, s2, off);
    }
    if ((tid & 31) == 0) { sred[tid >> 5] = s1; sred[8 + (tid >> 5)] = s2; }
    __syncthreads();
    if (tid == 0) {
        float a = 0.f, b = 0.f;
        for (int w = 0; w < 8; w++) { a += sred[w]; b += sred[8 + w]; }
        float mu = a * (1.f / DD);
        float var = b * (1.f / DD) - mu * mu;
        sred[16] = mu;
        sred[17] = rsqrtf(var + 1e-5f);
    }
    __syncthreads();
    const float mu = sred[16], rstd = sred[17];

    // normalized values (register-resident)
    float n0[4], n1[4];
#pragma unroll
    for (int s = 0; s < 4; s++) {
        float2 gv = __ldg((const float2*)(gamma + s * SD + d0));
        float2 bv = __ldg((const float2*)(beta  + s * SD + d0));
        n0[s] = (xv[s].x - mu) * rstd * gv.x + bv.x;
        n1[s] = (xv[s].y - mu) * rstd * gv.y + bv.y;
    }

    const size_t base = (size_t)blockIdx.x * DD;
#pragma unroll
    for (int t = 0; t < 4; t++) {
        float a0 = 0.f, a1 = 0.f, h0 = 0.f, h1 = 0.f;
#pragma unroll
        for (int s = 0; s < 4; s++) {
            float wa = g_sm.pre_a[s][t];
            float wh = g_sm.pre_h[s][t];
            a0 += wa * n0[s];  a1 += wa * n1[s];
            h0 += wh * xv[s].x; h1 += wh * xv[s].y;
        }
        *(uint32_t*)(g_Aa + base + t * SD + d0) = packbf2(a0, a1);
        *(uint32_t*)(g_Ah + base + t * SD + d0) = packbf2(h0, h1);
    }
}

// ---------------- fused bf16 mma.sync GEMM + final epilogue ----------------
// out[m, t*512+dd] = bias~ + sum_s Rw[s][t]*x[m, s*512+dd] + GEMM(m, p)
// GEMM: [A_a | A_h](16384x4096) @ g_Wc^T, CTA tile 128x128(p), BK=64, 64 chunks,
// 3-stage cp.async, 8 warps (4m x 2n), warp tile 32x64.
__global__ void __launch_bounds__(256, 2) gemm_kernel(const float* __restrict__ x,
                                                      float* __restrict__ out) {
    extern __shared__ __align__(128) char dsm[];

    const int tid  = threadIdx.x;
    const int wid  = tid >> 5;
    const int lane = tid & 31;
    const int nb = blockIdx.x, mbk = blockIdx.y;
    const int m0 = mbk * 128, n0 = nb * 128;
    const int dd0 = nb * 32;

    const uint32_t smem_base = smem_u32(dsm);

    const int lrow = tid >> 3;       // 0..31
    const int lcol = tid & 7;        // 0..7

    const int wm = wid & 3;
    const int wn = wid >> 2;
    const int mwarp = wm * 32, nwarp = wn * 64;

    const int lrow16 = lane & 15;
    const int lkhalf = (lane >> 4) * 16;

    float acc[2][8][4];
#pragma unroll
    for (int i = 0; i < 2; i++)
#pragma unroll
        for (int j = 0; j < 8; j++)
#pragma unroll
            for (int q = 0; q < 4; q++) acc[i][j][q] = 0.f;

    auto load_stage = [&](int stage, int chunk) {
        const uint32_t st = smem_base + stage * STAGE_BYTES;
        const __nv_bfloat16* Ap;
        if (chunk < 32)
            Ap = g_Aa + (size_t)(m0 + lrow) * DD + chunk * BK + lcol * 8;
        else
            Ap = g_Ah + (size_t)(m0 + lrow) * DD + (chunk - 32) * BK + lcol * 8;
        const __nv_bfloat16* Bp = g_Wc + (size_t)(n0 + lrow) * KTOT + chunk * BK + lcol * 8;
#pragma unroll
        for (int j = 0; j < 4; j++) {
            int r = lrow + 32 * j;
            cp_async16(st + SW128(r * 128 + lcol * 16), Ap + (size_t)(32 * j) * DD);
            cp_async16(st + 16384 + SW128(r * 128 + lcol * 16), Bp + (size_t)(32 * j) * KTOT);
        }
        cp_commit();
    };

    load_stage(0, 0);
    load_stage(1, 1);

    for (int c = 0; c < NK_CHUNKS; c++) {
        if (c < NK_CHUNKS - 2) cp_wait<1>(); else cp_wait<0>();
        __syncthreads();
        if (c + 2 < NK_CHUNKS) load_stage((c + 2) % STAGES, c + 2);

        const uint32_t stA = smem_base + (c % STAGES) * STAGE_BYTES;
        const uint32_t stB = stA + 16384;
#pragma unroll
        for (int ks = 0; ks < 4; ks++) {
            const int kb = ks * 32 + lkhalf;
            uint32_t af[2][4], bf[4][4];
#pragma unroll
            for (int i = 0; i < 2; i++)
                ldm_x4(af[i], stA + SW128((mwarp + i * 16 + lrow16) * 128 + kb));
#pragma unroll
            for (int j = 0; j < 4; j++)
                ldm_x4(bf[j], stB + SW128((nwarp + j * 16 + lrow16) * 128 + kb));
#pragma unroll
            for (int i = 0; i < 2; i++)
#pragma unroll
                for (int j = 0; j < 4; j++) {
                    mma16816(acc[i][j * 2 + 0], af[i], bf[j][0], bf[j][2]);
                    mma16816(acc[i][j * 2 + 1], af[i], bf[j][1], bf[j][3]);
                }
        }
    }

    // fused epilogue: out = acc + bias~ + residual-mix of x
    const int erow = lane >> 2;
    const int ecol = (lane & 3) * 2;
#pragma unroll
    for (int j = 0; j < 8; j++) {
        const int colT = nwarp + j * 8 + ecol;      // 0..127 within CTA tile
        const int t  = colT >> 5;                   // output stream
        const int dd = dd0 + (colT & 31);           // within-stream feature idx
        const float2 bv = *(const float2*)(g_bias + n0 + colT);
        float rw[4];
#pragma unroll
        for (int s = 0; s < 4; s++) rw[s] = g_sm.Rw[s][t];
#pragma unroll
        for (int i = 0; i < 2; i++) {
#pragma unroll
            for (int rr = 0; rr < 2; rr++) {
                const int m = m0 + mwarp + i * 16 + erow + rr * 8;
                const float* xr = x + (size_t)m * DD + dd;
                float o0 = acc[i][j][rr * 2 + 0] + bv.x;
                float o1 = acc[i][j][rr * 2 + 1] + bv.y;
#pragma unroll
                for (int s = 0; s < 4; s++) {
                    float2 xv = *(const float2*)(xr + s * SD);
                    o0 += rw[s] * xv.x;
                    o1 += rw[s] * xv.y;
                }
                *(float2*)(out + (size_t)m * DD + t * SD + dd) = make_float2(o0, o1);
            }
        }
    }
}

// ---------------- launch ----------------
extern "C" void kernel_launch(void* const* d_in, const int* in_sizes, int n_in,
                              void* d_out, int out_size) {
    const float* x     = (const float*)d_in[0];
    const float* g     = (const float*)d_in[1];
    const float* b     = (const float*)d_in[2];
    const float* Wa    = (const float*)d_in[3];
    const float* ba    = (const float*)d_in[4];
    const float* Wh    = (const float*)d_in[5];
    const float* bh    = (const float*)d_in[6];
    const float* pre_a = (const float*)d_in[7];
    const float* pre_h = (const float*)d_in[8];
    const float* res_a = (const float*)d_in[9];
    const float* post_a= (const float*)d_in[10];
    const float* sc_a  = (const float*)d_in[11];
    const float* res_h = (const float*)d_in[12];
    const float* post_h= (const float*)d_in[13];
    const float* sc_h  = (const float*)d_in[14];
    const float* cm    = (const float*)d_in[15];
    float* out = (float*)d_out;

    cudaFuncSetAttribute(gemm_kernel, cudaFuncAttributeMaxDynamicSharedMemorySize, DYN_SMEM);

    small_kernel<<<1, 32>>>(pre_a, pre_h, res_a, post_a, sc_a, res_h, post_h, sc_h, cm);
    bias_kernel<<<8, 256>>>(ba, bh);
    wtrans_kernel<<<dim3(64, 64, 2), dim3(32, 8)>>>(Wa, Wh);
    pre_kernel<<<MROWS, 256>>>(x, g, b);
    gemm_kernel<<<dim3(16, 128), 256, DYN_SMEM>>>(x, out);
}